// round 9
// baseline (speedup 1.0000x reference)
#include <cuda_runtime.h>

#define N_MAX 128
#define BB 4
#define BH 136
#define BW 200
#define OUT 56
#define CO 14
#define IMG_H 544
#define IMG_W 800
#define BF_STRIDE (1 + 4 + BB * CO * CO) /* 789 */

// Per-ROI paste region: 512 x 256 px, 32-px aligned anchor. Covers every
// nonzero output pixel (proof in header comment of paste kernel).
#define RGN_W 512
#define RGN_H 256
#define XT 4    /* x tiles of 128 px */
#define YT 8    /* y tiles of 32 rows */

#define CPR (IMG_W / 32)            /* 25 zero-chunks per image row */
#define CHUNKS (IMG_H * CPR)        /* 13600 chunks per roi */

// Padded mask storage: per ROI 58 rows x 64 pitch, data at [1..56][1..56],
// zero border; cols 58..63 stay .bss-zero. ~1.9 MB.
#define MROWS 58
#define MPITCH 64
__device__ float g_mpad[N_MAX * MROWS * MPITCH];

// ---------------------------------------------------------------------------
// Kernel 1: fused roi_align + coeff upsample + softmax + sigmoid (padded out).
// Grid (n_roi, 7), block 256.
// ---------------------------------------------------------------------------
__global__ void masks_kernel(const float* __restrict__ bases,
                             const float* __restrict__ bf) {
    int n = blockIdx.x;
    int chunk = blockIdx.y;
    const float* row = bf + (size_t)n * BF_STRIDE;
    float* mp = g_mpad + (size_t)n * MROWS * MPITCH;

    if (chunk == 0) {
        int t = threadIdx.x;
        if (t < MROWS) {
            mp[t] = 0.0f;
            mp[57 * MPITCH + t] = 0.0f;
        } else if (t < MROWS + 112) {
            int k = t - MROWS;
            int r = 1 + (k >> 1);
            int c = (k & 1) ? 57 : 0;
            mp[r * MPITCH + c] = 0.0f;
        }
    }

    __shared__ float s_top[BB * CO * CO];
    for (int i = threadIdx.x; i < BB * CO * CO; i += blockDim.x)
        s_top[i] = row[5 + i];
    __syncthreads();

    int bidx = (int)row[0];
    float bx0 = row[1], by0 = row[2], bx1 = row[3], by1 = row[4];
    const float* feat = bases + (size_t)bidx * (BB * BH * BW);

    float sx0 = bx0 * 0.25f - 0.5f;
    float sy0 = by0 * 0.25f - 0.5f;
    float sx1 = bx1 * 0.25f - 0.5f;
    float sy1 = by1 * 0.25f - 0.5f;
    float bwd = (sx1 - sx0) * (1.0f / OUT);
    float bhd = (sy1 - sy0) * (1.0f / OUT);

    int p0 = chunk * 448;
    for (int t = threadIdx.x; t < 448; t += blockDim.x) {
        int p = p0 + t;
        int i = p / OUT;
        int j = p - i * OUT;

        float ys = sy0 + (i + 0.5f) * bhd;
        float xs = sx0 + (j + 0.5f) * bwd;
        bool valid = (ys >= -1.0f) && (ys <= (float)BH) &&
                     (xs >= -1.0f) && (xs <= (float)BW);
        float yc = fminf(fmaxf(ys, 0.0f), (float)(BH - 1));
        float xc = fminf(fmaxf(xs, 0.0f), (float)(BW - 1));
        int yl = min((int)yc, BH - 2);
        int xl = min((int)xc, BW - 2);
        float ly = yc - (float)yl, hy = 1.0f - ly;
        float lx = xc - (float)xl, hx = 1.0f - lx;

        float cy = fminf(fmaxf((i + 0.5f) * 0.25f - 0.5f, 0.0f), (float)(CO - 1));
        float cx = fminf(fmaxf((j + 0.5f) * 0.25f - 0.5f, 0.0f), (float)(CO - 1));
        int cyl = min((int)cy, CO - 2);
        int cxl = min((int)cx, CO - 2);
        float ty = cy - (float)cyl, sy = 1.0f - ty;
        float tx = cx - (float)cxl, sx = 1.0f - tx;

        float roi[BB], cf[BB];
#pragma unroll
        for (int b = 0; b < BB; b++) {
            const float* f = feat + b * BH * BW + yl * BW + xl;
            float fll = __ldg(f);
            float flh = __ldg(f + 1);
            float fhl = __ldg(f + BW);
            float fhh = __ldg(f + BW + 1);
            float v = hy * (hx * fll + lx * flh) + ly * (hx * fhl + lx * fhh);
            roi[b] = valid ? v : 0.0f;

            const float* tp = s_top + b * CO * CO + cyl * CO + cxl;
            cf[b] = sy * (sx * tp[0] + tx * tp[1]) + ty * (sx * tp[CO] + tx * tp[CO + 1]);
        }

        float m = fmaxf(fmaxf(cf[0], cf[1]), fmaxf(cf[2], cf[3]));
        float e0 = __expf(cf[0] - m), e1 = __expf(cf[1] - m);
        float e2 = __expf(cf[2] - m), e3 = __expf(cf[3] - m);
        float inv = 1.0f / (e0 + e1 + e2 + e3);
        float dot = (roi[0] * e0 + roi[1] * e1 + roi[2] * e2 + roi[3] * e3) * inv;
        mp[(i + 1) * MPITCH + (j + 1)] = 1.0f / (1.0f + __expf(-dot));
    }
}

// Region anchor helpers — MUST be identical in fill and paste.
__device__ __forceinline__ int region_xs(float x0) {
    return max(0, ((int)floorf(x0) - 8)) & ~31;
}
__device__ __forceinline__ int region_ys(float y0) {
    return max(0, (int)floorf(y0) - 8);
}

// ---------------------------------------------------------------------------
// Kernel F: zero-fill of everything OUTSIDE each ROI's 512x256 region.
// One 32-px chunk (8x float4) per thread; region chunks are skipped (paste
// owns them). Pure store kernel. Grid (ceil(CHUNKS/256), n_roi), block 256.
// ---------------------------------------------------------------------------
__global__ void __launch_bounds__(256)
fill_kernel(const float* __restrict__ bf, float4* __restrict__ out) {
    int n = blockIdx.y;
    int ci = blockIdx.x * 256 + threadIdx.x;
    if (ci >= CHUNKS) return;

    int y = ci / CPR;
    int xc = (ci - y * CPR) * 32;

    const float* row = bf + (size_t)n * BF_STRIDE;
    float x0 = __ldg(row + 1), y0 = __ldg(row + 2);
    int xs = region_xs(x0);
    int ysr = region_ys(y0);

    // Chunk fully inside the paste region -> paste writes it.
    if (y >= ysr && y < ysr + RGN_H && xc >= xs && xc < xs + RGN_W) return;

    const float4 z = make_float4(0.f, 0.f, 0.f, 0.f);
    float4* p = out + ((size_t)n * (IMG_H * IMG_W) + (size_t)y * IMG_W + xc) / 4;
#pragma unroll
    for (int k = 0; k < 8; k++) p[k] = z;
}

// ---------------------------------------------------------------------------
// Kernel 2: paste. Writes its ENTIRE 512x256 region (zeros included) so its
// writes are disjoint from fill_kernel's. Thread = 4x4 px patch; x-LUT
// computed once, reused for 4 rows; dead threads/rows store zeros directly.
// Grid (XT, YT, n_roi), block (32, 8).
// ---------------------------------------------------------------------------
__global__ void __launch_bounds__(256)
paste_box_kernel(const float* __restrict__ bf, float* __restrict__ out) {
    int n = blockIdx.z;
    const float* row = bf + (size_t)n * BF_STRIDE;
    float x0 = __ldg(row + 1), y0 = __ldg(row + 2);
    float x1 = __ldg(row + 3), y1 = __ldg(row + 4);

    int xs = region_xs(x0);
    int ysr = region_ys(y0);

    int x = xs + (blockIdx.x * 32 + threadIdx.x) * 4;
    if (x + 3 >= IMG_W) return;                 // outside image: nobody's duty

    float inv_w = __fdividef((float)OUT, x1 - x0);
    float fxs = ((float)x + 0.5f - x0) * inv_w - 0.5f;
    bool xlive = (fxs + 3.0f * inv_w > -1.0f) && (fxs < (float)OUT);

    int c[4];
    float w0[4], w1[4];
    if (xlive) {
#pragma unroll
        for (int k = 0; k < 4; k++) {
            float fx = fxs + (float)k * inv_w;
            bool valid = (fx > -1.0f) && (fx < (float)OUT);
            float fmx = floorf(fx);
            float wx1 = fx - fmx, wx0 = 1.0f - wx1;
            c[k] = min(max((int)fmx, -1), 61) + 1;   // 0..62 always in pitch
            w0[k] = valid ? wx0 : 0.0f;
            w1[k] = valid ? wx1 : 0.0f;
        }
    }

    float inv_h = __fdividef((float)OUT, y1 - y0);
    int ybase = ysr + blockIdx.y * 32 + threadIdx.y * 4;
    const float* Mb = g_mpad + (size_t)n * MROWS * MPITCH;
    float* orow = out + (size_t)n * (IMG_H * IMG_W) + (size_t)ybase * IMG_W + x;

    const float4 z4 = make_float4(0.f, 0.f, 0.f, 0.f);

#pragma unroll
    for (int r = 0; r < 4; r++, orow += IMG_W) {
        int y = ybase + r;
        if (y >= IMG_H) break;                  // outside image

        if (!xlive) { *(float4*)orow = z4; continue; }

        float fy = ((float)y + 0.5f - y0) * inv_h - 0.5f;
        if (fy <= -1.0f || fy >= (float)OUT) { *(float4*)orow = z4; continue; }

        float fmy = floorf(fy);
        float wy1 = fy - fmy, wy0 = 1.0f - wy1;
        const float* M0 = Mb + ((int)fmy + 1) * MPITCH;
        const float* M1 = M0 + MPITCH;

        float v[4];
#pragma unroll
        for (int k = 0; k < 4; k++) {
            float a = w0[k] * __ldg(M0 + c[k]) + w1[k] * __ldg(M0 + c[k] + 1);
            float b = w0[k] * __ldg(M1 + c[k]) + w1[k] * __ldg(M1 + c[k] + 1);
            v[k] = wy0 * a + wy1 * b;
        }
        *(float4*)orow = make_float4(v[0], v[1], v[2], v[3]);
    }
}

// ---------------------------------------------------------------------------
// Static side stream + fork/join events (module init; not device allocations).
// ---------------------------------------------------------------------------
struct HxRes {
    cudaStream_t side;
    cudaEvent_t fork, join;
    HxRes() {
        cudaStreamCreateWithFlags(&side, cudaStreamNonBlocking);
        cudaEventCreateWithFlags(&fork, cudaEventDisableTiming);
        cudaEventCreateWithFlags(&join, cudaEventDisableTiming);
    }
};
static HxRes hx;

extern "C" void kernel_launch(void* const* d_in, const int* in_sizes, int n_in,
                              void* d_out, int out_size) {
    const float* bases = (const float*)d_in[0];
    const float* bf = (const float*)d_in[1];
    int n_roi = in_sizes[1] / BF_STRIDE;
    if (n_roi > N_MAX) n_roi = N_MAX;

    // Branch A (side stream): masks -> paste (writes ONLY region pixels).
    cudaEventRecord(hx.fork, 0);
    cudaStreamWaitEvent(hx.side, hx.fork, 0);

    dim3 mgrid(n_roi, 7);
    masks_kernel<<<mgrid, 256, 0, hx.side>>>(bases, bf);

    dim3 pblock(32, 8);
    dim3 pgrid(XT, YT, n_roi);
    paste_box_kernel<<<pgrid, pblock, 0, hx.side>>>(bf, (float*)d_out);
    cudaEventRecord(hx.join, hx.side);

    // Branch B (main stream): zero-fill of everything outside the regions.
    // Writes are disjoint from paste's, so the branches can run concurrently.
    dim3 fgrid((CHUNKS + 255) / 256, n_roi);
    fill_kernel<<<fgrid, 256>>>(bf, (float4*)d_out);

    cudaStreamWaitEvent(0, hx.join, 0);
}

// round 10
// speedup vs baseline: 1.1607x; 1.1607x over previous
#include <cuda_runtime.h>

#define N_MAX 128
#define BB 4
#define BH 136
#define BW 200
#define OUT 56
#define CO 14
#define IMG_H 544
#define IMG_W 800
#define BF_STRIDE (1 + 4 + BB * CO * CO) /* 789 */

// Per-ROI paste region: 384 x 256 px. xs >= x0-8, covers x < x0+376 (> max
// nonzero x0+322); ysr >= y0-4, covers y < ysr+256 (> y1+5). Tiles: 3 x 4
// blocks of 128 x 64 px.
#define XT 3
#define YT 4

// Padded mask storage: per ROI 58 rows x 64 pitch, data at [1..56][1..56],
// zero border; cols 58..63 stay .bss-zero. ~1.9 MB.
#define MROWS 58
#define MPITCH 64
__device__ float g_mpad[N_MAX * MROWS * MPITCH];

// ---------------------------------------------------------------------------
// Kernel 1: fused roi_align + coeff upsample + softmax + sigmoid (padded out).
// Grid (n_roi, 7), block 256.
// ---------------------------------------------------------------------------
__global__ void masks_kernel(const float* __restrict__ bases,
                             const float* __restrict__ bf) {
    int n = blockIdx.x;
    int chunk = blockIdx.y;
    const float* row = bf + (size_t)n * BF_STRIDE;
    float* mp = g_mpad + (size_t)n * MROWS * MPITCH;

    if (chunk == 0) {
        int t = threadIdx.x;
        if (t < MROWS) {
            mp[t] = 0.0f;                     // row 0
            mp[57 * MPITCH + t] = 0.0f;       // row 57
        } else if (t < MROWS + 112) {
            int k = t - MROWS;
            int r = 1 + (k >> 1);
            int c = (k & 1) ? 57 : 0;
            mp[r * MPITCH + c] = 0.0f;
        }
    }

    __shared__ float s_top[BB * CO * CO];
    for (int i = threadIdx.x; i < BB * CO * CO; i += blockDim.x)
        s_top[i] = row[5 + i];
    __syncthreads();

    int bidx = (int)row[0];
    float bx0 = row[1], by0 = row[2], bx1 = row[3], by1 = row[4];
    const float* feat = bases + (size_t)bidx * (BB * BH * BW);

    float sx0 = bx0 * 0.25f - 0.5f;
    float sy0 = by0 * 0.25f - 0.5f;
    float sx1 = bx1 * 0.25f - 0.5f;
    float sy1 = by1 * 0.25f - 0.5f;
    float bwd = (sx1 - sx0) * (1.0f / OUT);
    float bhd = (sy1 - sy0) * (1.0f / OUT);

    int p0 = chunk * 448;
    for (int t = threadIdx.x; t < 448; t += blockDim.x) {
        int p = p0 + t;
        int i = p / OUT;
        int j = p - i * OUT;

        float ys = sy0 + (i + 0.5f) * bhd;
        float xs = sx0 + (j + 0.5f) * bwd;
        bool valid = (ys >= -1.0f) && (ys <= (float)BH) &&
                     (xs >= -1.0f) && (xs <= (float)BW);
        float yc = fminf(fmaxf(ys, 0.0f), (float)(BH - 1));
        float xc = fminf(fmaxf(xs, 0.0f), (float)(BW - 1));
        int yl = min((int)yc, BH - 2);
        int xl = min((int)xc, BW - 2);
        float ly = yc - (float)yl, hy = 1.0f - ly;
        float lx = xc - (float)xl, hx = 1.0f - lx;

        float cy = fminf(fmaxf((i + 0.5f) * 0.25f - 0.5f, 0.0f), (float)(CO - 1));
        float cx = fminf(fmaxf((j + 0.5f) * 0.25f - 0.5f, 0.0f), (float)(CO - 1));
        int cyl = min((int)cy, CO - 2);
        int cxl = min((int)cx, CO - 2);
        float ty = cy - (float)cyl, sy = 1.0f - ty;
        float tx = cx - (float)cxl, sx = 1.0f - tx;

        float roi[BB], cf[BB];
#pragma unroll
        for (int b = 0; b < BB; b++) {
            const float* f = feat + b * BH * BW + yl * BW + xl;
            float fll = __ldg(f);
            float flh = __ldg(f + 1);
            float fhl = __ldg(f + BW);
            float fhh = __ldg(f + BW + 1);
            float v = hy * (hx * fll + lx * flh) + ly * (hx * fhl + lx * fhh);
            roi[b] = valid ? v : 0.0f;

            const float* tp = s_top + b * CO * CO + cyl * CO + cxl;
            cf[b] = sy * (sx * tp[0] + tx * tp[1]) + ty * (sx * tp[CO] + tx * tp[CO + 1]);
        }

        float m = fmaxf(fmaxf(cf[0], cf[1]), fmaxf(cf[2], cf[3]));
        float e0 = __expf(cf[0] - m), e1 = __expf(cf[1] - m);
        float e2 = __expf(cf[2] - m), e3 = __expf(cf[3] - m);
        float inv = 1.0f / (e0 + e1 + e2 + e3);
        float dot = (roi[0] * e0 + roi[1] * e1 + roi[2] * e2 + roi[3] * e3) * inv;
        mp[(i + 1) * MPITCH + (j + 1)] = 1.0f / (1.0f + __expf(-dot));
    }
}

// ---------------------------------------------------------------------------
// Kernel 2: paste. Thread owns a 4x8 px patch (4 x-positions, 8 rows).
// Block-uniform early exit for 128x64 slabs dead in y or x (memset covers
// them). x-LUT computed once per thread, reused across 8 rows; per-row fy is
// incremental. Grid (XT, YT, n_roi), block (32, 8).
// ---------------------------------------------------------------------------
__global__ void __launch_bounds__(256)
paste_box_kernel(const float* __restrict__ bf, float* __restrict__ out) {
    int n = blockIdx.z;
    const float* row = bf + (size_t)n * BF_STRIDE;
    float x0 = __ldg(row + 1), y0 = __ldg(row + 2);
    float x1 = __ldg(row + 3), y1 = __ldg(row + 4);

    int xs = max(0, ((int)floorf(x0) - 4)) & ~3;
    int ysr = max(0, (int)floorf(y0) - 4);

    float inv_h = __fdividef((float)OUT, y1 - y0);
    float inv_w = __fdividef((float)OUT, x1 - x0);

    // ---- Block-uniform slab liveness (fy/fx monotone increasing) ----
    int slabY = ysr + blockIdx.y * 64;
    float fyTop = ((float)slabY + 0.5f - y0) * inv_h - 0.5f;
    float fyBot = fyTop + 63.0f * inv_h;
    if (fyBot <= -1.0f || fyTop >= (float)OUT) return;

    int slabX = xs + blockIdx.x * 128;
    float fxL = ((float)slabX + 0.5f - x0) * inv_w - 0.5f;
    float fxR = fxL + 127.0f * inv_w;
    if (fxR <= -1.0f || fxL >= (float)OUT) return;

    // ---- Per-thread x setup ----
    int x = slabX + threadIdx.x * 4;
    if (x + 3 >= IMG_W) return;

    float fxs = fxL + (float)(threadIdx.x * 4) * inv_w;
    bool xlive = (fxs + 3.0f * inv_w > -1.0f) && (fxs < (float)OUT);
    if (!xlive) return;                       // memset covers these columns

    int c[4];
    float w0[4], w1[4];
#pragma unroll
    for (int k = 0; k < 4; k++) {
        float fx = fxs + (float)k * inv_w;
        bool valid = (fx > -1.0f) && (fx < (float)OUT);
        float fmx = floorf(fx);
        float wx1 = fx - fmx, wx0 = 1.0f - wx1;
        c[k] = min(max((int)fmx, -1), 61) + 1;   // 0..62 stays in pitch
        w0[k] = valid ? wx0 : 0.0f;
        w1[k] = valid ? wx1 : 0.0f;
    }

    // ---- 8 rows, incremental fy ----
    int ybase = slabY + threadIdx.y * 8;
    float fy = fyTop + (float)(threadIdx.y * 8) * inv_h;
    const float* Mb = g_mpad + (size_t)n * MROWS * MPITCH;
    float* orow = out + (size_t)n * (IMG_H * IMG_W) + (size_t)ybase * IMG_W + x;

#pragma unroll
    for (int r = 0; r < 8; r++, orow += IMG_W, fy += inv_h) {
        int y = ybase + r;
        if (y >= IMG_H) break;
        if (fy <= -1.0f || fy >= (float)OUT) continue;   // memset covers

        float fmy = floorf(fy);
        float wy1 = fy - fmy, wy0 = 1.0f - wy1;
        const float* M0 = Mb + ((int)fmy + 1) * MPITCH;
        const float* M1 = M0 + MPITCH;

        float v[4];
#pragma unroll
        for (int k = 0; k < 4; k++) {
            float a = w0[k] * __ldg(M0 + c[k]) + w1[k] * __ldg(M0 + c[k] + 1);
            float b = w0[k] * __ldg(M1 + c[k]) + w1[k] * __ldg(M1 + c[k] + 1);
            v[k] = wy0 * a + wy1 * b;
        }
        *(float4*)orow = make_float4(v[0], v[1], v[2], v[3]);
    }
}

extern "C" void kernel_launch(void* const* d_in, const int* in_sizes, int n_in,
                              void* d_out, int out_size) {
    const float* bases = (const float*)d_in[0];
    const float* bf = (const float*)d_in[1];
    int n_roi = in_sizes[1] / BF_STRIDE;
    if (n_roi > N_MAX) n_roi = N_MAX;

    // Serial: memset is the only fast way to write the bulk zeros, and
    // overlap schemes net negative on this graph (R5/R7/R9 evidence).
    cudaMemsetAsync(d_out, 0, (size_t)out_size * sizeof(float));

    dim3 mgrid(n_roi, 7);
    masks_kernel<<<mgrid, 256>>>(bases, bf);

    dim3 pblock(32, 8);
    dim3 pgrid(XT, YT, n_roi);
    paste_box_kernel<<<pgrid, pblock>>>(bf, (float*)d_out);
}

// round 11
// speedup vs baseline: 1.2333x; 1.0625x over previous
#include <cuda_runtime.h>

#define N_MAX 128
#define BB 4
#define BH 136
#define BW 200
#define OUT 56
#define CO 14
#define IMG_H 544
#define IMG_W 800
#define BF_STRIDE (1 + 4 + BB * CO * CO) /* 789 */

// Per-ROI paste region: 384 x 256 px; tiles of 128 px x 32 rows.
#define XT 3
#define YT 8

// Padded mask storage: per ROI 58 rows x 64 pitch, data at [1..56][1..56],
// zero border; cols 58..63 stay .bss-zero. ~1.9 MB.
#define MROWS 58
#define MPITCH 64
__device__ float g_mpad[N_MAX * MROWS * MPITCH];

// ---------------------------------------------------------------------------
// Kernel 1: fused roi_align + coeff upsample + softmax + sigmoid (padded out).
// Grid (n_roi, 7), block 256.
// ---------------------------------------------------------------------------
__global__ void masks_kernel(const float* __restrict__ bases,
                             const float* __restrict__ bf) {
    int n = blockIdx.x;
    int chunk = blockIdx.y;
    const float* row = bf + (size_t)n * BF_STRIDE;
    float* mp = g_mpad + (size_t)n * MROWS * MPITCH;

    if (chunk == 0) {
        int t = threadIdx.x;
        if (t < MROWS) {
            mp[t] = 0.0f;                     // row 0
            mp[57 * MPITCH + t] = 0.0f;       // row 57
        } else if (t < MROWS + 112) {
            int k = t - MROWS;
            int r = 1 + (k >> 1);
            int c = (k & 1) ? 57 : 0;
            mp[r * MPITCH + c] = 0.0f;
        }
    }

    __shared__ float s_top[BB * CO * CO];
    for (int i = threadIdx.x; i < BB * CO * CO; i += blockDim.x)
        s_top[i] = row[5 + i];
    __syncthreads();

    int bidx = (int)row[0];
    float bx0 = row[1], by0 = row[2], bx1 = row[3], by1 = row[4];
    const float* feat = bases + (size_t)bidx * (BB * BH * BW);

    float sx0 = bx0 * 0.25f - 0.5f;
    float sy0 = by0 * 0.25f - 0.5f;
    float sx1 = bx1 * 0.25f - 0.5f;
    float sy1 = by1 * 0.25f - 0.5f;
    float bwd = (sx1 - sx0) * (1.0f / OUT);
    float bhd = (sy1 - sy0) * (1.0f / OUT);

    int p0 = chunk * 448;
    for (int t = threadIdx.x; t < 448; t += blockDim.x) {
        int p = p0 + t;
        int i = p / OUT;
        int j = p - i * OUT;

        float ys = sy0 + (i + 0.5f) * bhd;
        float xs = sx0 + (j + 0.5f) * bwd;
        bool valid = (ys >= -1.0f) && (ys <= (float)BH) &&
                     (xs >= -1.0f) && (xs <= (float)BW);
        float yc = fminf(fmaxf(ys, 0.0f), (float)(BH - 1));
        float xc = fminf(fmaxf(xs, 0.0f), (float)(BW - 1));
        int yl = min((int)yc, BH - 2);
        int xl = min((int)xc, BW - 2);
        float ly = yc - (float)yl, hy = 1.0f - ly;
        float lx = xc - (float)xl, hx = 1.0f - lx;

        float cy = fminf(fmaxf((i + 0.5f) * 0.25f - 0.5f, 0.0f), (float)(CO - 1));
        float cx = fminf(fmaxf((j + 0.5f) * 0.25f - 0.5f, 0.0f), (float)(CO - 1));
        int cyl = min((int)cy, CO - 2);
        int cxl = min((int)cx, CO - 2);
        float ty = cy - (float)cyl, sy = 1.0f - ty;
        float tx = cx - (float)cxl, sx = 1.0f - tx;

        float roi[BB], cf[BB];
#pragma unroll
        for (int b = 0; b < BB; b++) {
            const float* f = feat + b * BH * BW + yl * BW + xl;
            float fll = __ldg(f);
            float flh = __ldg(f + 1);
            float fhl = __ldg(f + BW);
            float fhh = __ldg(f + BW + 1);
            float v = hy * (hx * fll + lx * flh) + ly * (hx * fhl + lx * fhh);
            roi[b] = valid ? v : 0.0f;

            const float* tp = s_top + b * CO * CO + cyl * CO + cxl;
            cf[b] = sy * (sx * tp[0] + tx * tp[1]) + ty * (sx * tp[CO] + tx * tp[CO + 1]);
        }

        float m = fmaxf(fmaxf(cf[0], cf[1]), fmaxf(cf[2], cf[3]));
        float e0 = __expf(cf[0] - m), e1 = __expf(cf[1] - m);
        float e2 = __expf(cf[2] - m), e3 = __expf(cf[3] - m);
        float inv = 1.0f / (e0 + e1 + e2 + e3);
        float dot = (roi[0] * e0 + roi[1] * e1 + roi[2] * e2 + roi[3] * e3) * inv;
        mp[(i + 1) * MPITCH + (j + 1)] = 1.0f / (1.0f + __expf(-dot));
    }
}

// ---------------------------------------------------------------------------
// Kernel 2: paste. R8 structure (4x4 patch per thread, 2400 blocks) + block-
// uniform slab liveness test (128x32 slab, fy/fx monotone -> corner tests).
// Dead slabs exit in ~20 instructions; memset covers their zeros.
// Grid (XT, YT, n_roi), block (32, 8).
// ---------------------------------------------------------------------------
__global__ void __launch_bounds__(256)
paste_box_kernel(const float* __restrict__ bf, float* __restrict__ out) {
    int n = blockIdx.z;
    const float* row = bf + (size_t)n * BF_STRIDE;
    float x0 = __ldg(row + 1), y0 = __ldg(row + 2);
    float x1 = __ldg(row + 3), y1 = __ldg(row + 4);

    int xs = max(0, ((int)floorf(x0) - 4)) & ~3;
    int ysr = max(0, (int)floorf(y0) - 4);

    float inv_h = __fdividef((float)OUT, y1 - y0);
    float inv_w = __fdividef((float)OUT, x1 - x0);

    // ---- Block-uniform slab liveness (128 px x 32 rows) ----
    int slabY = ysr + blockIdx.y * 32;
    float fyTop = ((float)slabY + 0.5f - y0) * inv_h - 0.5f;
    if (fyTop + 31.0f * inv_h <= -1.0f || fyTop >= (float)OUT) return;

    int slabX = xs + blockIdx.x * 128;
    float fxL = ((float)slabX + 0.5f - x0) * inv_w - 0.5f;
    if (fxL + 127.0f * inv_w <= -1.0f || fxL >= (float)OUT) return;

    // ---- Per-thread x setup (4 px) ----
    int x = slabX + threadIdx.x * 4;
    if (x + 3 >= IMG_W) return;

    float fxs = fxL + (float)(threadIdx.x * 4) * inv_w;
    if (fxs + 3.0f * inv_w <= -1.0f || fxs >= (float)OUT) return;  // memset covers

    int c[4];
    float w0[4], w1[4];
#pragma unroll
    for (int k = 0; k < 4; k++) {
        float fx = fxs + (float)k * inv_w;
        bool valid = (fx > -1.0f) && (fx < (float)OUT);
        float fmx = floorf(fx);
        float wx1 = fx - fmx, wx0 = 1.0f - wx1;
        c[k] = min(max((int)fmx, -1), 61) + 1;   // 0..62 stays in pitch
        w0[k] = valid ? wx0 : 0.0f;
        w1[k] = valid ? wx1 : 0.0f;
    }

    // ---- 4 rows ----
    int ybase = slabY + threadIdx.y * 4;
    float fy = fyTop + (float)(threadIdx.y * 4) * inv_h;
    const float* Mb = g_mpad + (size_t)n * MROWS * MPITCH;
    float* orow = out + (size_t)n * (IMG_H * IMG_W) + (size_t)ybase * IMG_W + x;

#pragma unroll
    for (int r = 0; r < 4; r++, orow += IMG_W, fy += inv_h) {
        int y = ybase + r;
        if (y >= IMG_H) break;
        if (fy <= -1.0f || fy >= (float)OUT) continue;   // memset covers

        float fmy = floorf(fy);
        float wy1 = fy - fmy, wy0 = 1.0f - wy1;
        const float* M0 = Mb + ((int)fmy + 1) * MPITCH;
        const float* M1 = M0 + MPITCH;

        float v[4];
#pragma unroll
        for (int k = 0; k < 4; k++) {
            float a = w0[k] * __ldg(M0 + c[k]) + w1[k] * __ldg(M0 + c[k] + 1);
            float b = w0[k] * __ldg(M1 + c[k]) + w1[k] * __ldg(M1 + c[k] + 1);
            v[k] = wy0 * a + wy1 * b;
        }
        *(float4*)orow = make_float4(v[0], v[1], v[2], v[3]);
    }
}

extern "C" void kernel_launch(void* const* d_in, const int* in_sizes, int n_in,
                              void* d_out, int out_size) {
    const float* bases = (const float*)d_in[0];
    const float* bf = (const float*)d_in[1];
    int n_roi = in_sizes[1] / BF_STRIDE;
    if (n_roi > N_MAX) n_roi = N_MAX;

    // Serial: memset is the only fast way to write the bulk zeros; overlap
    // schemes net negative on this graph (R5/R7/R9 evidence).
    cudaMemsetAsync(d_out, 0, (size_t)out_size * sizeof(float));

    dim3 mgrid(n_roi, 7);
    masks_kernel<<<mgrid, 256>>>(bases, bf);

    dim3 pblock(32, 8);
    dim3 pgrid(XT, YT, n_roi);
    paste_box_kernel<<<pgrid, pblock>>>(bf, (float*)d_out);
}

// round 12
// speedup vs baseline: 1.2564x; 1.0187x over previous
#include <cuda_runtime.h>

#define N_MAX 128
#define BB 4
#define BH 136
#define BW 200
#define OUT 56
#define CO 14
#define IMG_H 544
#define IMG_W 800
#define BF_STRIDE (1 + 4 + BB * CO * CO) /* 789 */

// Per-ROI paste region: 384 x 256 px; tiles of 128 px x 32 rows.
#define XT 3
#define YT 8

// Mask storage as horizontal PAIRS: g_mpair[n][r][c] = (m[r][c], m[r][c+1]),
// padded layout (data rows 1..56, cols 1..56; borders zero). 58 x 64 pairs
// per ROI (~2.9 MB total). One aligned LDG.64 per bilinear x-tap pair.
#define MROWS 58
#define MPITCH 64
__device__ float2 g_mpair[N_MAX * MROWS * MPITCH];

// ---------------------------------------------------------------------------
// Kernel 1: fused roi_align + coeff upsample + softmax + sigmoid, staged in
// smem per 8-row chunk, emitted as float2 pairs. Grid (n_roi, 7), block 256.
// ---------------------------------------------------------------------------
__global__ void masks_kernel(const float* __restrict__ bases,
                             const float* __restrict__ bf) {
    int n = blockIdx.x;
    int chunk = blockIdx.y;                  // 0..6, 8 mask rows each
    const float* row = bf + (size_t)n * BF_STRIDE;
    float2* mpair = g_mpair + (size_t)n * MROWS * MPITCH;

    __shared__ float s_top[BB * CO * CO];
    __shared__ float s_m[8][MPITCH];         // padded cols 0..63, this chunk

    for (int i = threadIdx.x; i < BB * CO * CO; i += blockDim.x)
        s_top[i] = row[5 + i];
    // zero the staging tile (borders + unused cols)
    for (int i = threadIdx.x; i < 8 * MPITCH; i += blockDim.x)
        ((float*)s_m)[i] = 0.0f;

    // Border rows of the padded layout (rows 0 and 57): zero pairs.
    if (chunk == 0 && threadIdx.x < 2 * MPITCH) {
        int r = (threadIdx.x >> 6) ? 57 : 0;
        int c = threadIdx.x & 63;
        mpair[r * MPITCH + c] = make_float2(0.0f, 0.0f);
    }
    __syncthreads();

    int bidx = (int)row[0];
    float bx0 = row[1], by0 = row[2], bx1 = row[3], by1 = row[4];
    const float* feat = bases + (size_t)bidx * (BB * BH * BW);

    float sx0 = bx0 * 0.25f - 0.5f;
    float sy0 = by0 * 0.25f - 0.5f;
    float sx1 = bx1 * 0.25f - 0.5f;
    float sy1 = by1 * 0.25f - 0.5f;
    float bwd = (sx1 - sx0) * (1.0f / OUT);
    float bhd = (sy1 - sy0) * (1.0f / OUT);

    int p0 = chunk * 448;
    for (int t = threadIdx.x; t < 448; t += blockDim.x) {
        int p = p0 + t;
        int i = p / OUT;
        int j = p - i * OUT;

        float ys = sy0 + (i + 0.5f) * bhd;
        float xs = sx0 + (j + 0.5f) * bwd;
        bool valid = (ys >= -1.0f) && (ys <= (float)BH) &&
                     (xs >= -1.0f) && (xs <= (float)BW);
        float yc = fminf(fmaxf(ys, 0.0f), (float)(BH - 1));
        float xc = fminf(fmaxf(xs, 0.0f), (float)(BW - 1));
        int yl = min((int)yc, BH - 2);
        int xl = min((int)xc, BW - 2);
        float ly = yc - (float)yl, hy = 1.0f - ly;
        float lx = xc - (float)xl, hx = 1.0f - lx;

        float cy = fminf(fmaxf((i + 0.5f) * 0.25f - 0.5f, 0.0f), (float)(CO - 1));
        float cx = fminf(fmaxf((j + 0.5f) * 0.25f - 0.5f, 0.0f), (float)(CO - 1));
        int cyl = min((int)cy, CO - 2);
        int cxl = min((int)cx, CO - 2);
        float ty = cy - (float)cyl, sy = 1.0f - ty;
        float tx = cx - (float)cxl, sx = 1.0f - tx;

        float roi[BB], cf[BB];
#pragma unroll
        for (int b = 0; b < BB; b++) {
            const float* f = feat + b * BH * BW + yl * BW + xl;
            float fll = __ldg(f);
            float flh = __ldg(f + 1);
            float fhl = __ldg(f + BW);
            float fhh = __ldg(f + BW + 1);
            float v = hy * (hx * fll + lx * flh) + ly * (hx * fhl + lx * fhh);
            roi[b] = valid ? v : 0.0f;

            const float* tp = s_top + b * CO * CO + cyl * CO + cxl;
            cf[b] = sy * (sx * tp[0] + tx * tp[1]) + ty * (sx * tp[CO] + tx * tp[CO + 1]);
        }

        float m = fmaxf(fmaxf(cf[0], cf[1]), fmaxf(cf[2], cf[3]));
        float e0 = __expf(cf[0] - m), e1 = __expf(cf[1] - m);
        float e2 = __expf(cf[2] - m), e3 = __expf(cf[3] - m);
        float inv = 1.0f / (e0 + e1 + e2 + e3);
        float dot = (roi[0] * e0 + roi[1] * e1 + roi[2] * e2 + roi[3] * e3) * inv;
        s_m[i - chunk * 8][j + 1] = 1.0f / (1.0f + __expf(-dot));
    }
    __syncthreads();

    // Emit pairs: padded rows 1+chunk*8 .. 8+chunk*8, cols 0..63.
    float2* dstp = mpair + (size_t)(1 + chunk * 8) * MPITCH;
    for (int idx = threadIdx.x; idx < 8 * MPITCH; idx += blockDim.x) {
        int r = idx >> 6;
        int c = idx & 63;
        float a = s_m[r][c];
        float b = (c < 63) ? s_m[r][c + 1] : 0.0f;
        dstp[r * MPITCH + c] = make_float2(a, b);
    }
}

// ---------------------------------------------------------------------------
// Kernel 2: paste. 4x4 patch per thread, slab early-exit, and ONE LDG.64 per
// bilinear tap pair (float2 mask pairs). Grid (XT, YT, n_roi), block (32, 8).
// ---------------------------------------------------------------------------
__global__ void __launch_bounds__(256)
paste_box_kernel(const float* __restrict__ bf, float* __restrict__ out) {
    int n = blockIdx.z;
    const float* row = bf + (size_t)n * BF_STRIDE;
    float x0 = __ldg(row + 1), y0 = __ldg(row + 2);
    float x1 = __ldg(row + 3), y1 = __ldg(row + 4);

    int xs = max(0, ((int)floorf(x0) - 4)) & ~3;
    int ysr = max(0, (int)floorf(y0) - 4);

    float inv_h = __fdividef((float)OUT, y1 - y0);
    float inv_w = __fdividef((float)OUT, x1 - x0);

    // ---- Block-uniform slab liveness (128 px x 32 rows) ----
    int slabY = ysr + blockIdx.y * 32;
    float fyTop = ((float)slabY + 0.5f - y0) * inv_h - 0.5f;
    if (fyTop + 31.0f * inv_h <= -1.0f || fyTop >= (float)OUT) return;

    int slabX = xs + blockIdx.x * 128;
    float fxL = ((float)slabX + 0.5f - x0) * inv_w - 0.5f;
    if (fxL + 127.0f * inv_w <= -1.0f || fxL >= (float)OUT) return;

    // ---- Per-thread x setup (4 px) ----
    int x = slabX + threadIdx.x * 4;
    if (x + 3 >= IMG_W) return;

    float fxs = fxL + (float)(threadIdx.x * 4) * inv_w;
    if (fxs + 3.0f * inv_w <= -1.0f || fxs >= (float)OUT) return;  // memset covers

    int c[4];
    float w0[4], w1[4];
#pragma unroll
    for (int k = 0; k < 4; k++) {
        float fx = fxs + (float)k * inv_w;
        bool valid = (fx > -1.0f) && (fx < (float)OUT);
        float fmx = floorf(fx);
        float wx1 = fx - fmx, wx0 = 1.0f - wx1;
        c[k] = min(max((int)fmx, -1), 61) + 1;   // 0..62
        w0[k] = valid ? wx0 : 0.0f;
        w1[k] = valid ? wx1 : 0.0f;
    }

    // ---- 4 rows ----
    int ybase = slabY + threadIdx.y * 4;
    float fy = fyTop + (float)(threadIdx.y * 4) * inv_h;
    const float2* Mb = g_mpair + (size_t)n * MROWS * MPITCH;
    float* orow = out + (size_t)n * (IMG_H * IMG_W) + (size_t)ybase * IMG_W + x;

#pragma unroll
    for (int r = 0; r < 4; r++, orow += IMG_W, fy += inv_h) {
        int y = ybase + r;
        if (y >= IMG_H) break;
        if (fy <= -1.0f || fy >= (float)OUT) continue;   // memset covers

        float fmy = floorf(fy);
        float wy1 = fy - fmy, wy0 = 1.0f - wy1;
        const float2* M0 = Mb + ((int)fmy + 1) * MPITCH;
        const float2* M1 = M0 + MPITCH;

        float v[4];
#pragma unroll
        for (int k = 0; k < 4; k++) {
            float2 q0 = __ldg(M0 + c[k]);
            float2 q1 = __ldg(M1 + c[k]);
            v[k] = wy0 * (w0[k] * q0.x + w1[k] * q0.y) +
                   wy1 * (w0[k] * q1.x + w1[k] * q1.y);
        }
        *(float4*)orow = make_float4(v[0], v[1], v[2], v[3]);
    }
}

extern "C" void kernel_launch(void* const* d_in, const int* in_sizes, int n_in,
                              void* d_out, int out_size) {
    const float* bases = (const float*)d_in[0];
    const float* bf = (const float*)d_in[1];
    int n_roi = in_sizes[1] / BF_STRIDE;
    if (n_roi > N_MAX) n_roi = N_MAX;

    // Serial: memset is the only fast way to write the bulk zeros; overlap
    // schemes net negative on this graph (R5/R7/R9 evidence).
    cudaMemsetAsync(d_out, 0, (size_t)out_size * sizeof(float));

    dim3 mgrid(n_roi, 7);
    masks_kernel<<<mgrid, 256>>>(bases, bf);

    dim3 pblock(32, 8);
    dim3 pgrid(XT, YT, n_roi);
    paste_box_kernel<<<pgrid, pblock>>>(bf, (float*)d_out);
}